// round 16
// baseline (speedup 1.0000x reference)
#include <cuda_runtime.h>
#include <cuda_bf16.h>
#include <cuda_fp16.h>
#include <stdint.h>

#define B_ 8
#define T_ 2048
#define D_ 1024
#define SCALE_ 0.03125f   // 1/sqrt(1024)

// k_qk: stage = A tile 8KB + B tiles 16KB
#define QK_STAGE 24576
// k_av: stage = S half-tile 8KB + XT tile 16KB
#define AV_STAGE 24576

// ---------------------------------------------------------------------------
// Scratch — tiled, pre-swizzled layouts
//   g_Xh : bf16 X tiles  [b][t64:32][kc:16] of 64r x 64c (8KB each)
//   g_St : f16  S tiles  [b][tb:16][kc:32]  of 128r x 64c (16KB each)
//   g_XTt: f16  XT tiles [b][nb:8][kc:32]   of 128r(d) x 64c(t) (16KB each)
// ---------------------------------------------------------------------------
__device__ __nv_bfloat16 g_Xh [(size_t)B_ * 32 * 16 * 4096];
__device__ __half        g_St [(size_t)B_ * 16 * 32 * 8192];
__device__ __half        g_XTt[(size_t)B_ * 8  * 32 * 8192];
__device__ __half        g_Ch [(size_t)B_ * T_ * D_];     // unnorm context f16

// ---------------------------------------------------------------------------
// Helpers
// ---------------------------------------------------------------------------
__device__ __forceinline__ uint32_t smem_u32(const void* p) {
    uint32_t a;
    asm("{ .reg .u64 t; cvta.to.shared.u64 t, %1; cvt.u32.u64 %0, t; }"
        : "=r"(a) : "l"(p));
    return a;
}

#define MBAR_INIT(addr, cnt) \
    asm volatile("mbarrier.init.shared.b64 [%0], %1;" :: "r"(addr), "r"(cnt) : "memory")

__device__ __forceinline__ void bar_expect(uint32_t mbar, uint32_t bytes) {
    asm volatile("mbarrier.arrive.expect_tx.shared.b64 _, [%0], %1;"
                 :: "r"(mbar), "r"(bytes) : "memory");
}

__device__ __forceinline__ void bar_wait(uint32_t mbar, uint32_t phase) {
    asm volatile(
        "{\n\t.reg .pred P;\n"
        "W%=:\n\t"
        "mbarrier.try_wait.parity.shared.b64 P, [%0], %1;\n\t"
        "@!P bra W%=;\n\t}"
        :: "r"(mbar), "r"(phase) : "memory");
}

__device__ __forceinline__ void bulk_ld(uint32_t dst, const void* src,
                                        uint32_t bytes, uint32_t mbar) {
    asm volatile(
        "cp.async.bulk.shared::cluster.global.mbarrier::complete_tx::bytes "
        "[%0], [%1], %2, [%3];"
        :: "r"(dst), "l"(src), "r"(bytes), "r"(mbar) : "memory");
}

__device__ __forceinline__ void ldmx4(uint32_t& r0, uint32_t& r1,
                                      uint32_t& r2, uint32_t& r3, uint32_t addr) {
    asm volatile("ldmatrix.sync.aligned.m8n8.x4.shared.b16 {%0,%1,%2,%3}, [%4];"
                 : "=r"(r0), "=r"(r1), "=r"(r2), "=r"(r3) : "r"(addr));
}

__device__ __forceinline__ void mma_bf16(float* c, const uint32_t* a,
                                         uint32_t b0, uint32_t b1) {
    asm volatile(
        "mma.sync.aligned.m16n8k16.row.col.f32.bf16.bf16.f32 "
        "{%0,%1,%2,%3}, {%4,%5,%6,%7}, {%8,%9}, {%0,%1,%2,%3};"
        : "+f"(c[0]), "+f"(c[1]), "+f"(c[2]), "+f"(c[3])
        : "r"(a[0]), "r"(a[1]), "r"(a[2]), "r"(a[3]), "r"(b0), "r"(b1));
}

__device__ __forceinline__ void mma_f16(float* c, const uint32_t* a,
                                        uint32_t b0, uint32_t b1) {
    asm volatile(
        "mma.sync.aligned.m16n8k16.row.col.f32.f16.f16.f32 "
        "{%0,%1,%2,%3}, {%4,%5,%6,%7}, {%8,%9}, {%0,%1,%2,%3};"
        : "+f"(c[0]), "+f"(c[1]), "+f"(c[2]), "+f"(c[3])
        : "r"(a[0]), "r"(a[1]), "r"(a[2]), "r"(a[3]), "r"(b0), "r"(b1));
}

__device__ __forceinline__ uint32_t sw128(uint32_t off) {
    return off ^ ((off >> 3) & 0x70);
}

__device__ __forceinline__ float softplusf_(float v) {
    return v > 20.f ? v : log1pf(__expf(v));
}
__device__ __forceinline__ float gelu_tanh_(float v) {
    float u = 0.7978845608028654f * (v + 0.044715f * v * v * v);
    return 0.5f * v * (1.f + tanhf(u));
}

// FFMA-pipe 2^z (|rel err| < ~7e-4 on z in [-30,30]); z=-64 underflows to ~0
__device__ __forceinline__ float fexp2p(float z) {
    float m = z + 12582912.f;         // 1.5*2^23 magic: rint in mantissa
    float n = m - 12582912.f;
    float f = z - n;
    float p = 0.0096180f;
    p = fmaf(p, f, 0.0555041f);
    p = fmaf(p, f, 0.2402265f);
    p = fmaf(p, f, 0.6931472f);
    p = fmaf(p, f, 1.0f);
    return __int_as_float(__float_as_int(p) + (__float_as_int(m) << 23));
}

// ---------------------------------------------------------------------------
// Kernel 0: convert x -> tiled bf16 X tiles + tiled f16 XT tiles
// ---------------------------------------------------------------------------
__global__ __launch_bounds__(256) void k_cvt(const float* __restrict__ x) {
    __shared__ float tile[32][33];
    const int b  = blockIdx.z;
    const int t0 = blockIdx.x * 32;
    const int d0 = blockIdx.y * 32;
    const int lx = threadIdx.x;
    const int ly = threadIdx.y;
    const float* X = x + (size_t)b * T_ * D_;

#pragma unroll
    for (int r = 0; r < 2; r++) {
        const int t = t0 + ly + r * 16;
        const int d = d0 + lx * 2;
        float2 v = *(const float2*)(X + (size_t)t * D_ + d);
        __nv_bfloat162 h = __floats2bfloat162_rn(v.x, v.y);
        const size_t tile_idx = (size_t)((b * 32 + (t >> 6)) * 16 + (d >> 6));
        char* dst = (char*)g_Xh + tile_idx * 8192
                  + sw128((uint32_t)((t & 63) * 128 + (d & 63) * 2));
        *(uint32_t*)dst = *(uint32_t*)&h;
        tile[ly + r * 16][lx * 2 + 0] = v.x;
        tile[ly + r * 16][lx * 2 + 1] = v.y;
    }
    __syncthreads();
#pragma unroll
    for (int r = 0; r < 2; r++) {
        const int d  = d0 + ly + r * 16;
        const int tp = t0 + lx * 2;
        __half2 h = __floats2half2_rn(tile[lx * 2 + 0][ly + r * 16],
                                      tile[lx * 2 + 1][ly + r * 16]);
        const size_t tile_idx = (size_t)((b * 8 + (d >> 7)) * 32 + (tp >> 6));
        char* dst = (char*)g_XTt + tile_idx * 16384
                  + sw128((uint32_t)((d & 127) * 128 + (tp & 63) * 2));
        *(uint32_t*)dst = *(uint32_t*)&h;
    }
}

// ---------------------------------------------------------------------------
// MMA cores: CTA 64(m) x 128(n), 8 warps 2m x 4n of 32x32
// ---------------------------------------------------------------------------
__device__ __forceinline__ void mma_chunk_qk(uint32_t sA, uint32_t sB,
                                             int warp_m, int warp_n, int lane,
                                             float c[2][4][4]) {
    const int rowsel = lane & 15;
    const int khalf  = (lane >> 4) * 16;
    const uint32_t a0 = sA + (warp_m * 32 + 0  + rowsel) * 128;
    const uint32_t a1 = sA + (warp_m * 32 + 16 + rowsel) * 128;
    const uint32_t b0a = sB + (warp_n * 32 + 0  + rowsel) * 128;
    const uint32_t b1a = sB + (warp_n * 32 + 16 + rowsel) * 128;
    const uint32_t xa0 = ((warp_m * 32 + 0  + rowsel) & 7) << 4;
    const uint32_t xa1 = ((warp_m * 32 + 16 + rowsel) & 7) << 4;
    const uint32_t xb0 = ((warp_n * 32 + 0  + rowsel) & 7) << 4;
    const uint32_t xb1 = ((warp_n * 32 + 16 + rowsel) & 7) << 4;
#pragma unroll
    for (int ks = 0; ks < 4; ks++) {
        const uint32_t kb = ks * 32 + khalf;
        uint32_t a[2][4];
        ldmx4(a[0][0], a[0][1], a[0][2], a[0][3], a0 + (kb ^ xa0));
        ldmx4(a[1][0], a[1][1], a[1][2], a[1][3], a1 + (kb ^ xa1));
        uint32_t b[4][2];
        {
            uint32_t r0, r1, r2, r3;
            ldmx4(r0, r1, r2, r3, b0a + (kb ^ xb0));
            b[0][0] = r0; b[1][0] = r1; b[0][1] = r2; b[1][1] = r3;
            ldmx4(r0, r1, r2, r3, b1a + (kb ^ xb1));
            b[2][0] = r0; b[3][0] = r1; b[2][1] = r2; b[3][1] = r3;
        }
#pragma unroll
        for (int mi = 0; mi < 2; mi++)
#pragma unroll
            for (int ni = 0; ni < 4; ni++)
                mma_bf16(c[mi][ni], a[mi], b[ni][0], b[ni][1]);
    }
}

__device__ __forceinline__ void mma_chunk_av(uint32_t sA, uint32_t sB,
                                             int warp_m, int warp_n, int lane,
                                             float c[2][4][4]) {
    const int rowsel = lane & 15;
    const int khalf  = (lane >> 4) * 16;
    const uint32_t a0 = sA + (warp_m * 32 + 0  + rowsel) * 128;
    const uint32_t a1 = sA + (warp_m * 32 + 16 + rowsel) * 128;
    const uint32_t b0a = sB + (warp_n * 32 + 0  + rowsel) * 128;
    const uint32_t b1a = sB + (warp_n * 32 + 16 + rowsel) * 128;
    const uint32_t xa0 = ((warp_m * 32 + 0  + rowsel) & 7) << 4;
    const uint32_t xa1 = ((warp_m * 32 + 16 + rowsel) & 7) << 4;
    const uint32_t xb0 = ((warp_n * 32 + 0  + rowsel) & 7) << 4;
    const uint32_t xb1 = ((warp_n * 32 + 16 + rowsel) & 7) << 4;
#pragma unroll
    for (int ks = 0; ks < 4; ks++) {
        const uint32_t kb = ks * 32 + khalf;
        uint32_t a[2][4];
        ldmx4(a[0][0], a[0][1], a[0][2], a[0][3], a0 + (kb ^ xa0));
        ldmx4(a[1][0], a[1][1], a[1][2], a[1][3], a1 + (kb ^ xa1));
        uint32_t b[4][2];
        {
            uint32_t r0, r1, r2, r3;
            ldmx4(r0, r1, r2, r3, b0a + (kb ^ xb0));
            b[0][0] = r0; b[1][0] = r1; b[0][1] = r2; b[1][1] = r3;
            ldmx4(r0, r1, r2, r3, b1a + (kb ^ xb1));
            b[2][0] = r0; b[3][0] = r1; b[2][1] = r2; b[3][1] = r3;
        }
#pragma unroll
        for (int mi = 0; mi < 2; mi++)
#pragma unroll
            for (int ni = 0; ni < 4; ni++)
                mma_f16(c[mi][ni], a[mi], b[ni][0], b[ni][1]);
    }
}

// ---------------------------------------------------------------------------
// Kernel 1: S = exp(SCALE * X X^T) f16 tiled, strict causal.
// No denominator (cosine is scale-invariant). Hybrid MUFU/FFMA exp.
// ---------------------------------------------------------------------------
__global__ __launch_bounds__(256, 3) void k_qk_mma() {
    const int sb  = blockIdx.x;
    const int tb6 = blockIdx.y;
    const int b   = blockIdx.z;
    if (sb > (tb6 >> 1)) return;

    extern __shared__ __align__(1024) char smem[];
    __shared__ __align__(8) uint64_t bars[3];
    const uint32_t sbase = smem_u32(smem);
    const int tid = threadIdx.x, lane = tid & 31, wid = tid >> 5;
    const int warp_m = wid & 1, warp_n = wid >> 1;

    if (tid == 0) {
#pragma unroll
        for (int s = 0; s < 3; s++) MBAR_INIT(smem_u32(&bars[s]), 1);
    }
    __syncthreads();

    const char* XA  = (const char*)g_Xh + (size_t)((b * 32 + tb6) * 16) * 8192;
    const char* XB0 = (const char*)g_Xh + (size_t)((b * 32 + 2 * sb) * 16) * 8192;
    const char* XB1 = (const char*)g_Xh + (size_t)((b * 32 + 2 * sb + 1) * 16) * 8192;

    float c[2][4][4];
#pragma unroll
    for (int mi = 0; mi < 2; mi++)
#pragma unroll
        for (int ni = 0; ni < 4; ni++)
#pragma unroll
            for (int k = 0; k < 4; k++) c[mi][ni][k] = 0.f;

    const int nIter = 16;
    if (tid == 0) {
#pragma unroll
        for (int s = 0; s < 2; s++) {
            const uint32_t mb = smem_u32(&bars[s]);
            const uint32_t st = sbase + s * QK_STAGE;
            bar_expect(mb, QK_STAGE);
            bulk_ld(st,         XA  + (size_t)s * 8192, 8192, mb);
            bulk_ld(st + 8192,  XB0 + (size_t)s * 8192, 8192, mb);
            bulk_ld(st + 16384, XB1 + (size_t)s * 8192, 8192, mb);
        }
    }

    for (int it = 0; it < nIter; ++it) {
        bar_wait(smem_u32(&bars[it % 3]), (uint32_t)((it / 3) & 1));
        __syncthreads();
        if (it + 2 < nIter && tid == 0) {
            const int ld = it + 2;
            const int s  = ld % 3;
            const uint32_t mb = smem_u32(&bars[s]);
            const uint32_t st = sbase + s * QK_STAGE;
            bar_expect(mb, QK_STAGE);
            bulk_ld(st,         XA  + (size_t)ld * 8192, 8192, mb);
            bulk_ld(st + 8192,  XB0 + (size_t)ld * 8192, 8192, mb);
            bulk_ld(st + 16384, XB1 + (size_t)ld * 8192, 8192, mb);
        }
        const uint32_t st = sbase + (it % 3) * QK_STAGE;
        mma_chunk_qk(st, st + 8192, warp_m, warp_n, lane, c);
    }

    // epilogue: masked exp2 (hybrid) -> f16 tiled S store
    const int quad = lane >> 2, qid = lane & 3;
    const float C2 = 0.045084219f;   // SCALE * log2(e)
    const size_t srow_base = (size_t)((b * 16 + (tb6 >> 1)) * 32);
#pragma unroll
    for (int mi = 0; mi < 2; mi++) {
#pragma unroll
        for (int h = 0; h < 2; h++) {
            const int row = warp_m * 32 + mi * 16 + quad + h * 8;
            const int t   = tb6 * 64 + row;
            const int row_local = (tb6 & 1) * 64 + row;
#pragma unroll
            for (int ni = 0; ni < 4; ni++) {
                const int col = warp_n * 32 + ni * 8 + qid * 2;
                const int s0  = sb * 128 + col;
                const float z0 = (s0 + 0 < t) ? c[mi][ni][2 * h + 0] * C2 : -64.f;
                const float z1 = (s0 + 1 < t) ? c[mi][ni][2 * h + 1] * C2 : -64.f;
                __half2 e;
                if ((h == 0) && (ni != 3)) {          // 3/8: FFMA-pipe poly
                    e = __floats2half2_rn(fexp2p(z0), fexp2p(z1));
                } else {                               // 5/8: MUFU
                    e = h2exp2(__floats2half2_rn(z0, z1));
                }
                const int kc = 2 * sb + (col >> 6);
                char* dst = (char*)g_St + (srow_base + kc) * 16384
                          + sw128((uint32_t)(row_local * 128 + (col & 63) * 2));
                *(uint32_t*)dst = *(uint32_t*)&e;
            }
        }
    }
}

// ---------------------------------------------------------------------------
// Kernel 3: unnormalized context c' = (S @ X) * 2^-6 (cosine scale-invariant).
// CTA 64(t) x 128(d), 8 warps 2m x 4n of 32x32, 24KB stages, 3 CTA/SM.
// ---------------------------------------------------------------------------
__global__ __launch_bounds__(256, 3) void k_av_mma() {
    const int nb  = blockIdx.x;
    const int tb6 = 31 - (int)blockIdx.y;       // heavy-first
    const int b   = blockIdx.z;

    extern __shared__ __align__(1024) char smem[];
    __shared__ __align__(8) uint64_t bars[3];
    const uint32_t sbase = smem_u32(smem);
    const int tid = threadIdx.x, lane = tid & 31, wid = tid >> 5;
    const int warp_m = wid & 1, warp_n = wid >> 1;

    if (tid == 0) {
#pragma unroll
        for (int s = 0; s < 3; s++) MBAR_INIT(smem_u32(&bars[s]), 1);
    }
    __syncthreads();

    const char* SA = (const char*)g_St
                   + (size_t)((b * 16 + (tb6 >> 1)) * 32) * 16384
                   + (size_t)(tb6 & 1) * 8192;
    const char* XB = (const char*)g_XTt + (size_t)((b * 8 + nb) * 32) * 16384;

    float c[2][4][4];
#pragma unroll
    for (int mi = 0; mi < 2; mi++)
#pragma unroll
        for (int ni = 0; ni < 4; ni++)
#pragma unroll
            for (int k = 0; k < 4; k++) c[mi][ni][k] = 0.f;

    const int nIter = ((tb6 >> 1) + 1) * 2;
    if (tid == 0) {
#pragma unroll
        for (int s = 0; s < 2; s++) {
            if (s < nIter) {
                const uint32_t mb = smem_u32(&bars[s]);
                const uint32_t st = sbase + s * AV_STAGE;
                bar_expect(mb, AV_STAGE);
                bulk_ld(st,        SA + (size_t)s * 16384, 8192,  mb);
                bulk_ld(st + 8192, XB + (size_t)s * 16384, 16384, mb);
            }
        }
    }

    for (int it = 0; it < nIter; ++it) {
        bar_wait(smem_u32(&bars[it % 3]), (uint32_t)((it / 3) & 1));
        __syncthreads();
        if (it + 2 < nIter && tid == 0) {
            const int ld = it + 2;
            const int s  = ld % 3;
            const uint32_t mb = smem_u32(&bars[s]);
            const uint32_t st = sbase + s * AV_STAGE;
            bar_expect(mb, AV_STAGE);
            bulk_ld(st,        SA + (size_t)ld * 16384, 8192,  mb);
            bulk_ld(st + 8192, XB + (size_t)ld * 16384, 16384, mb);
        }
        const uint32_t st = sbase + (it % 3) * AV_STAGE;
        mma_chunk_av(st, st + 8192, warp_m, warp_n, lane, c);
    }

    // epilogue: fixed 2^-6 scale (f16-range safety; cosine invariant), f16 store
    const int quad = lane >> 2, qid = lane & 3;
    const float SC = 0.015625f;
#pragma unroll
    for (int mi = 0; mi < 2; mi++) {
#pragma unroll
        for (int h = 0; h < 2; h++) {
            const int row = warp_m * 32 + mi * 16 + quad + h * 8;
            const int t   = tb6 * 64 + row;
            __half* crow = g_Ch + ((size_t)(b * T_ + t)) * D_ + nb * 128;
#pragma unroll
            for (int ni = 0; ni < 4; ni++) {
                const int col = warp_n * 32 + ni * 8 + qid * 2;
                __half2 hv = __floats2half2_rn(c[mi][ni][2 * h + 0] * SC,
                                               c[mi][ni][2 * h + 1] * SC);
                *(uint32_t*)(crow + col) = *(uint32_t*)&hv;
            }
        }
    }
}

// ---------------------------------------------------------------------------
// Kernel 4: cosine / novelty / gate / tanh-GELU (unnormalized f16 C)
// ---------------------------------------------------------------------------
__global__ __launch_bounds__(256) void k_epi(const float* __restrict__ x,
                                             const float* __restrict__ p_la,
                                             const float* __restrict__ p_ls,
                                             float* __restrict__ out) {
    const int row = blockIdx.x;
    const int tid = threadIdx.x;
    const float4 xv = *((const float4*)x + (size_t)row * 256 + tid);
    const uint2 cu  = *((const uint2*)g_Ch + (size_t)row * 256 + tid);
    float2 c01 = __half22float2(*(const __half2*)&cu.x);
    float2 c23 = __half22float2(*(const __half2*)&cu.y);

    float xx = xv.x * xv.x + xv.y * xv.y + xv.z * xv.z + xv.w * xv.w;
    float cc = c01.x * c01.x + c01.y * c01.y + c23.x * c23.x + c23.y * c23.y;
    float xc = xv.x * c01.x + xv.y * c01.y + xv.z * c23.x + xv.w * c23.y;

#pragma unroll
    for (int o = 16; o; o >>= 1) {
        xx += __shfl_down_sync(0xFFFFFFFFu, xx, o);
        cc += __shfl_down_sync(0xFFFFFFFFu, cc, o);
        xc += __shfl_down_sync(0xFFFFFFFFu, xc, o);
    }

    __shared__ float s_xx[8], s_cc[8], s_xc[8];
    __shared__ float s_gate;
    const int lane = tid & 31, w = tid >> 5;
    if (lane == 0) { s_xx[w] = xx; s_cc[w] = cc; s_xc[w] = xc; }
    __syncthreads();
    if (tid == 0) {
        float fxx = 0.f, fcc = 0.f, fxc = 0.f;
#pragma unroll
        for (int k = 0; k < 8; k++) { fxx += s_xx[k]; fcc += s_cc[k]; fxc += s_xc[k]; }
        const float nx = fmaxf(sqrtf(fxx), 1e-12f);
        const float nc = fmaxf(sqrtf(fcc), 1e-12f);
        const float cosv = fxc / (nx * nc);
        const float nov  = fminf(fmaxf(1.f - cosv, 0.f), 2.f) * 0.5f;
        const float alpha = softplusf_(*p_la);
        const float sigma = softplusf_(*p_ls);
        s_gate = 1.f + alpha * tanhf(sigma * nov);
    }
    __syncthreads();
    const float g = s_gate;

    float4 o;
    o.x = gelu_tanh_(xv.x * g);
    o.y = gelu_tanh_(xv.y * g);
    o.z = gelu_tanh_(xv.z * g);
    o.w = gelu_tanh_(xv.w * g);
    *((float4*)out + (size_t)row * 256 + tid) = o;
}

// ---------------------------------------------------------------------------
extern "C" void kernel_launch(void* const* d_in, const int* in_sizes, int n_in,
                              void* d_out, int out_size) {
    const float* x  = (const float*)d_in[0];
    const float* la = (const float*)d_in[1];
    const float* ls = (const float*)d_in[2];
    float* out = (float*)d_out;

    const int qk_smem = 3 * QK_STAGE;   // 73728
    const int av_smem = 3 * AV_STAGE;   // 73728
    cudaFuncSetAttribute(k_qk_mma, cudaFuncAttributeMaxDynamicSharedMemorySize, qk_smem);
    cudaFuncSetAttribute(k_av_mma, cudaFuncAttributeMaxDynamicSharedMemorySize, av_smem);

    dim3 gc(T_ / 32, D_ / 32, B_);
    k_cvt<<<gc, dim3(16, 16)>>>(x);

    dim3 g1(16, 32, B_);
    k_qk_mma<<<g1, 256, qk_smem>>>();

    dim3 g3(8, 32, B_);
    k_av_mma<<<g3, 256, av_smem>>>();

    k_epi<<<B_ * T_, 256>>>(x, la, ls, out);
}

// round 17
// speedup vs baseline: 1.0342x; 1.0342x over previous
#include <cuda_runtime.h>
#include <cuda_bf16.h>
#include <cuda_fp16.h>
#include <stdint.h>

#define B_ 8
#define T_ 2048
#define D_ 1024
#define SCALE_ 0.03125f   // 1/sqrt(1024)

#define QK_STAGE 24576
#define AV_STAGE 24576

// ---------------------------------------------------------------------------
// Scratch — tiled, pre-swizzled layouts
// ---------------------------------------------------------------------------
__device__ __nv_bfloat16 g_Xh [(size_t)B_ * 32 * 16 * 4096];
__device__ __half        g_St [(size_t)B_ * 16 * 32 * 8192];
__device__ __half        g_XTt[(size_t)B_ * 8  * 32 * 8192];
__device__ __half        g_Ch [(size_t)B_ * T_ * D_];     // unnorm context f16

// ---------------------------------------------------------------------------
// Helpers
// ---------------------------------------------------------------------------
__device__ __forceinline__ uint32_t smem_u32(const void* p) {
    uint32_t a;
    asm("{ .reg .u64 t; cvta.to.shared.u64 t, %1; cvt.u32.u64 %0, t; }"
        : "=r"(a) : "l"(p));
    return a;
}

#define MBAR_INIT(addr, cnt) \
    asm volatile("mbarrier.init.shared.b64 [%0], %1;" :: "r"(addr), "r"(cnt) : "memory")

__device__ __forceinline__ void bar_expect(uint32_t mbar, uint32_t bytes) {
    asm volatile("mbarrier.arrive.expect_tx.shared.b64 _, [%0], %1;"
                 :: "r"(mbar), "r"(bytes) : "memory");
}

__device__ __forceinline__ void bar_wait(uint32_t mbar, uint32_t phase) {
    asm volatile(
        "{\n\t.reg .pred P;\n"
        "W%=:\n\t"
        "mbarrier.try_wait.parity.shared.b64 P, [%0], %1;\n\t"
        "@!P bra W%=;\n\t}"
        :: "r"(mbar), "r"(phase) : "memory");
}

__device__ __forceinline__ void bulk_ld(uint32_t dst, const void* src,
                                        uint32_t bytes, uint32_t mbar) {
    asm volatile(
        "cp.async.bulk.shared::cluster.global.mbarrier::complete_tx::bytes "
        "[%0], [%1], %2, [%3];"
        :: "r"(dst), "l"(src), "r"(bytes), "r"(mbar) : "memory");
}

__device__ __forceinline__ void ldmx4(uint32_t& r0, uint32_t& r1,
                                      uint32_t& r2, uint32_t& r3, uint32_t addr) {
    asm volatile("ldmatrix.sync.aligned.m8n8.x4.shared.b16 {%0,%1,%2,%3}, [%4];"
                 : "=r"(r0), "=r"(r1), "=r"(r2), "=r"(r3) : "r"(addr));
}

__device__ __forceinline__ void mma_bf16(float* c, const uint32_t* a,
                                         uint32_t b0, uint32_t b1) {
    asm volatile(
        "mma.sync.aligned.m16n8k16.row.col.f32.bf16.bf16.f32 "
        "{%0,%1,%2,%3}, {%4,%5,%6,%7}, {%8,%9}, {%0,%1,%2,%3};"
        : "+f"(c[0]), "+f"(c[1]), "+f"(c[2]), "+f"(c[3])
        : "r"(a[0]), "r"(a[1]), "r"(a[2]), "r"(a[3]), "r"(b0), "r"(b1));
}

__device__ __forceinline__ void mma_f16(float* c, const uint32_t* a,
                                        uint32_t b0, uint32_t b1) {
    asm volatile(
        "mma.sync.aligned.m16n8k16.row.col.f32.f16.f16.f32 "
        "{%0,%1,%2,%3}, {%4,%5,%6,%7}, {%8,%9}, {%0,%1,%2,%3};"
        : "+f"(c[0]), "+f"(c[1]), "+f"(c[2]), "+f"(c[3])
        : "r"(a[0]), "r"(a[1]), "r"(a[2]), "r"(a[3]), "r"(b0), "r"(b1));
}

__device__ __forceinline__ uint32_t sw128(uint32_t off) {
    return off ^ ((off >> 3) & 0x70);
}

__device__ __forceinline__ float tanh_ap(float v) {
    float r;
    asm("tanh.approx.f32 %0, %1;" : "=f"(r) : "f"(v));
    return r;
}

__device__ __forceinline__ float softplusf_(float v) {
    return v > 20.f ? v : log1pf(__expf(v));
}
__device__ __forceinline__ float gelu_tanh_(float v) {
    float u = 0.7978845608028654f * (v + 0.044715f * v * v * v);
    return 0.5f * v * (1.f + tanh_ap(u));
}

// ---------------------------------------------------------------------------
// Kernel 0: convert x -> tiled bf16 X tiles + tiled f16 XT tiles
// ---------------------------------------------------------------------------
__global__ __launch_bounds__(256) void k_cvt(const float* __restrict__ x) {
    __shared__ float tile[32][33];
    const int b  = blockIdx.z;
    const int t0 = blockIdx.x * 32;
    const int d0 = blockIdx.y * 32;
    const int lx = threadIdx.x;
    const int ly = threadIdx.y;
    const float* X = x + (size_t)b * T_ * D_;

#pragma unroll
    for (int r = 0; r < 2; r++) {
        const int t = t0 + ly + r * 16;
        const int d = d0 + lx * 2;
        float2 v = *(const float2*)(X + (size_t)t * D_ + d);
        __nv_bfloat162 h = __floats2bfloat162_rn(v.x, v.y);
        const size_t tile_idx = (size_t)((b * 32 + (t >> 6)) * 16 + (d >> 6));
        char* dst = (char*)g_Xh + tile_idx * 8192
                  + sw128((uint32_t)((t & 63) * 128 + (d & 63) * 2));
        *(uint32_t*)dst = *(uint32_t*)&h;
        tile[ly + r * 16][lx * 2 + 0] = v.x;
        tile[ly + r * 16][lx * 2 + 1] = v.y;
    }
    __syncthreads();
#pragma unroll
    for (int r = 0; r < 2; r++) {
        const int d  = d0 + ly + r * 16;
        const int tp = t0 + lx * 2;
        __half2 h = __floats2half2_rn(tile[lx * 2 + 0][ly + r * 16],
                                      tile[lx * 2 + 1][ly + r * 16]);
        const size_t tile_idx = (size_t)((b * 8 + (d >> 7)) * 32 + (tp >> 6));
        char* dst = (char*)g_XTt + tile_idx * 16384
                  + sw128((uint32_t)((d & 127) * 128 + (tp & 63) * 2));
        *(uint32_t*)dst = *(uint32_t*)&h;
    }
}

// ---------------------------------------------------------------------------
// MMA cores: CTA 64(m) x 128(n), 8 warps 2m x 4n of 32x32
// ---------------------------------------------------------------------------
__device__ __forceinline__ void mma_chunk_qk(uint32_t sA, uint32_t sB,
                                             int warp_m, int warp_n, int lane,
                                             float c[2][4][4]) {
    const int rowsel = lane & 15;
    const int khalf  = (lane >> 4) * 16;
    const uint32_t a0 = sA + (warp_m * 32 + 0  + rowsel) * 128;
    const uint32_t a1 = sA + (warp_m * 32 + 16 + rowsel) * 128;
    const uint32_t b0a = sB + (warp_n * 32 + 0  + rowsel) * 128;
    const uint32_t b1a = sB + (warp_n * 32 + 16 + rowsel) * 128;
    const uint32_t xa0 = ((warp_m * 32 + 0  + rowsel) & 7) << 4;
    const uint32_t xa1 = ((warp_m * 32 + 16 + rowsel) & 7) << 4;
    const uint32_t xb0 = ((warp_n * 32 + 0  + rowsel) & 7) << 4;
    const uint32_t xb1 = ((warp_n * 32 + 16 + rowsel) & 7) << 4;
#pragma unroll
    for (int ks = 0; ks < 4; ks++) {
        const uint32_t kb = ks * 32 + khalf;
        uint32_t a[2][4];
        ldmx4(a[0][0], a[0][1], a[0][2], a[0][3], a0 + (kb ^ xa0));
        ldmx4(a[1][0], a[1][1], a[1][2], a[1][3], a1 + (kb ^ xa1));
        uint32_t b[4][2];
        {
            uint32_t r0, r1, r2, r3;
            ldmx4(r0, r1, r2, r3, b0a + (kb ^ xb0));
            b[0][0] = r0; b[1][0] = r1; b[0][1] = r2; b[1][1] = r3;
            ldmx4(r0, r1, r2, r3, b1a + (kb ^ xb1));
            b[2][0] = r0; b[3][0] = r1; b[2][1] = r2; b[3][1] = r3;
        }
#pragma unroll
        for (int mi = 0; mi < 2; mi++)
#pragma unroll
            for (int ni = 0; ni < 4; ni++)
                mma_bf16(c[mi][ni], a[mi], b[ni][0], b[ni][1]);
    }
}

__device__ __forceinline__ void mma_chunk_av(uint32_t sA, uint32_t sB,
                                             int warp_m, int warp_n, int lane,
                                             float c[2][4][4]) {
    const int rowsel = lane & 15;
    const int khalf  = (lane >> 4) * 16;
    const uint32_t a0 = sA + (warp_m * 32 + 0  + rowsel) * 128;
    const uint32_t a1 = sA + (warp_m * 32 + 16 + rowsel) * 128;
    const uint32_t b0a = sB + (warp_n * 32 + 0  + rowsel) * 128;
    const uint32_t b1a = sB + (warp_n * 32 + 16 + rowsel) * 128;
    const uint32_t xa0 = ((warp_m * 32 + 0  + rowsel) & 7) << 4;
    const uint32_t xa1 = ((warp_m * 32 + 16 + rowsel) & 7) << 4;
    const uint32_t xb0 = ((warp_n * 32 + 0  + rowsel) & 7) << 4;
    const uint32_t xb1 = ((warp_n * 32 + 16 + rowsel) & 7) << 4;
#pragma unroll
    for (int ks = 0; ks < 4; ks++) {
        const uint32_t kb = ks * 32 + khalf;
        uint32_t a[2][4];
        ldmx4(a[0][0], a[0][1], a[0][2], a[0][3], a0 + (kb ^ xa0));
        ldmx4(a[1][0], a[1][1], a[1][2], a[1][3], a1 + (kb ^ xa1));
        uint32_t b[4][2];
        {
            uint32_t r0, r1, r2, r3;
            ldmx4(r0, r1, r2, r3, b0a + (kb ^ xb0));
            b[0][0] = r0; b[1][0] = r1; b[0][1] = r2; b[1][1] = r3;
            ldmx4(r0, r1, r2, r3, b1a + (kb ^ xb1));
            b[2][0] = r0; b[3][0] = r1; b[2][1] = r2; b[3][1] = r3;
        }
#pragma unroll
        for (int mi = 0; mi < 2; mi++)
#pragma unroll
            for (int ni = 0; ni < 4; ni++)
                mma_f16(c[mi][ni], a[mi], b[ni][0], b[ni][1]);
    }
}

// ---------------------------------------------------------------------------
// Kernel 1: S = exp(SCALE * X X^T) f16 tiled, strict causal. Pure MUFU exp.
// ---------------------------------------------------------------------------
__global__ __launch_bounds__(256, 3) void k_qk_mma() {
    const int sb  = blockIdx.x;
    const int tb6 = blockIdx.y;
    const int b   = blockIdx.z;
    if (sb > (tb6 >> 1)) return;

    extern __shared__ __align__(1024) char smem[];
    __shared__ __align__(8) uint64_t bars[3];
    const uint32_t sbase = smem_u32(smem);
    const int tid = threadIdx.x, lane = tid & 31, wid = tid >> 5;
    const int warp_m = wid & 1, warp_n = wid >> 1;

    if (tid == 0) {
#pragma unroll
        for (int s = 0; s < 3; s++) MBAR_INIT(smem_u32(&bars[s]), 1);
    }
    __syncthreads();

    const char* XA  = (const char*)g_Xh + (size_t)((b * 32 + tb6) * 16) * 8192;
    const char* XB0 = (const char*)g_Xh + (size_t)((b * 32 + 2 * sb) * 16) * 8192;
    const char* XB1 = (const char*)g_Xh + (size_t)((b * 32 + 2 * sb + 1) * 16) * 8192;

    float c[2][4][4];
#pragma unroll
    for (int mi = 0; mi < 2; mi++)
#pragma unroll
        for (int ni = 0; ni < 4; ni++)
#pragma unroll
            for (int k = 0; k < 4; k++) c[mi][ni][k] = 0.f;

    const int nIter = 16;
    if (tid == 0) {
#pragma unroll
        for (int s = 0; s < 2; s++) {
            const uint32_t mb = smem_u32(&bars[s]);
            const uint32_t st = sbase + s * QK_STAGE;
            bar_expect(mb, QK_STAGE);
            bulk_ld(st,         XA  + (size_t)s * 8192, 8192, mb);
            bulk_ld(st + 8192,  XB0 + (size_t)s * 8192, 8192, mb);
            bulk_ld(st + 16384, XB1 + (size_t)s * 8192, 8192, mb);
        }
    }

    for (int it = 0; it < nIter; ++it) {
        bar_wait(smem_u32(&bars[it % 3]), (uint32_t)((it / 3) & 1));
        __syncthreads();
        if (it + 2 < nIter && tid == 0) {
            const int ld = it + 2;
            const int s  = ld % 3;
            const uint32_t mb = smem_u32(&bars[s]);
            const uint32_t st = sbase + s * QK_STAGE;
            bar_expect(mb, QK_STAGE);
            bulk_ld(st,         XA  + (size_t)ld * 8192, 8192, mb);
            bulk_ld(st + 8192,  XB0 + (size_t)ld * 8192, 8192, mb);
            bulk_ld(st + 16384, XB1 + (size_t)ld * 8192, 8192, mb);
        }
        const uint32_t st = sbase + (it % 3) * QK_STAGE;
        mma_chunk_qk(st, st + 8192, warp_m, warp_n, lane, c);
    }

    // epilogue: masked packed exp2 -> f16 tiled S store
    const int quad = lane >> 2, qid = lane & 3;
    const float C2 = 0.045084219f;   // SCALE * log2(e)
    const size_t srow_base = (size_t)((b * 16 + (tb6 >> 1)) * 32);
#pragma unroll
    for (int mi = 0; mi < 2; mi++) {
#pragma unroll
        for (int h = 0; h < 2; h++) {
            const int row = warp_m * 32 + mi * 16 + quad + h * 8;
            const int t   = tb6 * 64 + row;
            const int row_local = (tb6 & 1) * 64 + row;
#pragma unroll
            for (int ni = 0; ni < 4; ni++) {
                const int col = warp_n * 32 + ni * 8 + qid * 2;
                const int s0  = sb * 128 + col;
                const float z0 = (s0 + 0 < t) ? c[mi][ni][2 * h + 0] * C2 : -64.f;
                const float z1 = (s0 + 1 < t) ? c[mi][ni][2 * h + 1] * C2 : -64.f;
                __half2 e = h2exp2(__floats2half2_rn(z0, z1));
                const int kc = 2 * sb + (col >> 6);
                char* dst = (char*)g_St + (srow_base + kc) * 16384
                          + sw128((uint32_t)(row_local * 128 + (col & 63) * 2));
                *(uint32_t*)dst = *(uint32_t*)&e;
            }
        }
    }
}

// ---------------------------------------------------------------------------
// Kernel 3: unnormalized context c' = (S @ X) * 2^-6.
// CTA 64(t) x 128(d), exact causal K: nIter = tb6+1. 3 CTA/SM. Heavy-first.
// ---------------------------------------------------------------------------
__global__ __launch_bounds__(256, 3) void k_av_mma() {
    const int nb  = blockIdx.x;
    const int tb6 = 31 - (int)blockIdx.y;       // heavy-first
    const int b   = blockIdx.z;

    extern __shared__ __align__(1024) char smem[];
    __shared__ __align__(8) uint64_t bars[3];
    const uint32_t sbase = smem_u32(smem);
    const int tid = threadIdx.x, lane = tid & 31, wid = tid >> 5;
    const int warp_m = wid & 1, warp_n = wid >> 1;

    if (tid == 0) {
#pragma unroll
        for (int s = 0; s < 3; s++) MBAR_INIT(smem_u32(&bars[s]), 1);
    }
    __syncthreads();

    const char* SA = (const char*)g_St
                   + (size_t)((b * 16 + (tb6 >> 1)) * 32) * 16384
                   + (size_t)(tb6 & 1) * 8192;
    const char* XB = (const char*)g_XTt + (size_t)((b * 8 + nb) * 32) * 16384;

    float c[2][4][4];
#pragma unroll
    for (int mi = 0; mi < 2; mi++)
#pragma unroll
        for (int ni = 0; ni < 4; ni++)
#pragma unroll
            for (int k = 0; k < 4; k++) c[mi][ni][k] = 0.f;

    const int nIter = tb6 + 1;   // exact causal chunk count (rest all-masked)
    if (tid == 0) {
#pragma unroll
        for (int s = 0; s < 2; s++) {
            if (s < nIter) {
                const uint32_t mb = smem_u32(&bars[s]);
                const uint32_t st = sbase + s * AV_STAGE;
                bar_expect(mb, AV_STAGE);
                bulk_ld(st,        SA + (size_t)s * 16384, 8192,  mb);
                bulk_ld(st + 8192, XB + (size_t)s * 16384, 16384, mb);
            }
        }
    }

    for (int it = 0; it < nIter; ++it) {
        bar_wait(smem_u32(&bars[it % 3]), (uint32_t)((it / 3) & 1));
        __syncthreads();
        if (it + 2 < nIter && tid == 0) {
            const int ld = it + 2;
            const int s  = ld % 3;
            const uint32_t mb = smem_u32(&bars[s]);
            const uint32_t st = sbase + s * AV_STAGE;
            bar_expect(mb, AV_STAGE);
            bulk_ld(st,        SA + (size_t)ld * 16384, 8192,  mb);
            bulk_ld(st + 8192, XB + (size_t)ld * 16384, 16384, mb);
        }
        const uint32_t st = sbase + (it % 3) * AV_STAGE;
        mma_chunk_av(st, st + 8192, warp_m, warp_n, lane, c);
    }

    // epilogue: fixed 2^-6 scale, f16 store
    const int quad = lane >> 2, qid = lane & 3;
    const float SC = 0.015625f;
#pragma unroll
    for (int mi = 0; mi < 2; mi++) {
#pragma unroll
        for (int h = 0; h < 2; h++) {
            const int row = warp_m * 32 + mi * 16 + quad + h * 8;
            const int t   = tb6 * 64 + row;
            __half* crow = g_Ch + ((size_t)(b * T_ + t)) * D_ + nb * 128;
#pragma unroll
            for (int ni = 0; ni < 4; ni++) {
                const int col = warp_n * 32 + ni * 8 + qid * 2;
                __half2 hv = __floats2half2_rn(c[mi][ni][2 * h + 0] * SC,
                                               c[mi][ni][2 * h + 1] * SC);
                *(uint32_t*)(crow + col) = *(uint32_t*)&hv;
            }
        }
    }
}

// ---------------------------------------------------------------------------
// Kernel 4: cosine / novelty / gate / tanh-GELU (tanh.approx)
// ---------------------------------------------------------------------------
__global__ __launch_bounds__(256) void k_epi(const float* __restrict__ x,
                                             const float* __restrict__ p_la,
                                             const float* __restrict__ p_ls,
                                             float* __restrict__ out) {
    const int row = blockIdx.x;
    const int tid = threadIdx.x;
    const float4 xv = *((const float4*)x + (size_t)row * 256 + tid);
    const uint2 cu  = *((const uint2*)g_Ch + (size_t)row * 256 + tid);
    float2 c01 = __half22float2(*(const __half2*)&cu.x);
    float2 c23 = __half22float2(*(const __half2*)&cu.y);

    float xx = xv.x * xv.x + xv.y * xv.y + xv.z * xv.z + xv.w * xv.w;
    float cc = c01.x * c01.x + c01.y * c01.y + c23.x * c23.x + c23.y * c23.y;
    float xc = xv.x * c01.x + xv.y * c01.y + xv.z * c23.x + xv.w * c23.y;

#pragma unroll
    for (int o = 16; o; o >>= 1) {
        xx += __shfl_down_sync(0xFFFFFFFFu, xx, o);
        cc += __shfl_down_sync(0xFFFFFFFFu, cc, o);
        xc += __shfl_down_sync(0xFFFFFFFFu, xc, o);
    }

    __shared__ float s_xx[8], s_cc[8], s_xc[8];
    __shared__ float s_gate;
    const int lane = tid & 31, w = tid >> 5;
    if (lane == 0) { s_xx[w] = xx; s_cc[w] = cc; s_xc[w] = xc; }
    __syncthreads();
    if (tid == 0) {
        float fxx = 0.f, fcc = 0.f, fxc = 0.f;
#pragma unroll
        for (int k = 0; k < 8; k++) { fxx += s_xx[k]; fcc += s_cc[k]; fxc += s_xc[k]; }
        const float nx = fmaxf(sqrtf(fxx), 1e-12f);
        const float nc = fmaxf(sqrtf(fcc), 1e-12f);
        const float cosv = fxc / (nx * nc);
        const float nov  = fminf(fmaxf(1.f - cosv, 0.f), 2.f) * 0.5f;
        const float alpha = softplusf_(*p_la);
        const float sigma = softplusf_(*p_ls);
        s_gate = 1.f + alpha * tanh_ap(sigma * nov);
    }
    __syncthreads();
    const float g = s_gate;

    float4 o;
    o.x = gelu_tanh_(xv.x * g);
    o.y = gelu_tanh_(xv.y * g);
    o.z = gelu_tanh_(xv.z * g);
    o.w = gelu_tanh_(xv.w * g);
    *((float4*)out + (size_t)row * 256 + tid) = o;
}

// ---------------------------------------------------------------------------
extern "C" void kernel_launch(void* const* d_in, const int* in_sizes, int n_in,
                              void* d_out, int out_size) {
    const float* x  = (const float*)d_in[0];
    const float* la = (const float*)d_in[1];
    const float* ls = (const float*)d_in[2];
    float* out = (float*)d_out;

    const int qk_smem = 3 * QK_STAGE;
    const int av_smem = 3 * AV_STAGE;
    cudaFuncSetAttribute(k_qk_mma, cudaFuncAttributeMaxDynamicSharedMemorySize, qk_smem);
    cudaFuncSetAttribute(k_av_mma, cudaFuncAttributeMaxDynamicSharedMemorySize, av_smem);

    dim3 gc(T_ / 32, D_ / 32, B_);
    k_cvt<<<gc, dim3(16, 16)>>>(x);

    dim3 g1(16, 32, B_);
    k_qk_mma<<<g1, 256, qk_smem>>>();

    dim3 g3(8, 32, B_);
    k_av_mma<<<g3, 256, av_smem>>>();

    k_epi<<<B_ * T_, 256>>>(x, la, ls, out);
}